// round 14
// baseline (speedup 1.0000x reference)
#include <cuda_runtime.h>
#include <cuda_bf16.h>
#include <cstdint>
#include <cstddef>

#define NEDGES  1600000
#define NNODES  100000
#define OUTD    64
#define MTILE   128
#define THREADS 512
#define TPB     8
#define EDGE_BLOCKS 1563                               // 1562 full (8 tiles) + 1 tail (4)
#define NODE_BLOCKS ((NNODES + MTILE - 1) / MTILE)     // 782

// ---- edge kernel smem layout (fp16, double-buffered A) ----
#define E_BIAS 0          // 64 floats
#define E_DST  256        // 1024 ints
#define E_SRC  4352
#define E_BB   8448
#define E_A0   12544      // 128x128 fp16 (32KB), swizzled 256B rows
#define E_A1   (E_A0 + 32768)
#define E_B    (E_A1 + 32768)   // 64x128 fp16 (16KB)
#define E_SZ   (E_B + 16384)    // 94464

// ---- node kernel smem layout (fp16 single buffer) ----
#define N_BIAS 0
#define N_BB   256        // 128 ints
#define N_A    2048       // 32KB
#define N_B    (N_A + 32768)
#define N_SZ   (N_B + 16384)    // 51200

// ---- device scratch ----
__device__ float g_agg[(size_t)NNODES * OUTD];
__device__ int   g_src[NEDGES];
__device__ int   g_dst[NEDGES];
__device__ int   g_batch[NNODES];
__device__ __align__(16) unsigned short g_x16[(size_t)NNODES * 32];  // x in fp16
__device__ __align__(16) unsigned short g_u16[64 * 32];              // u in fp16
__device__ __align__(16) unsigned char g_w1f16[16384];   // W1 fp16, B^T swizzled
__device__ __align__(16) unsigned char g_w2f16[16384];   // W2 fp16, B^T swizzled

// ================= helpers =================
__device__ __forceinline__ uint32_t smem_u32(const void* p) {
    uint32_t a;
    asm("{ .reg .u64 t; cvta.to.shared.u64 t, %1; cvt.u32.u64 %0, t; }" : "=r"(a) : "l"(p));
    return a;
}
__device__ __forceinline__ uint32_t pack_f16(float a, float b) {
    uint32_t w;
    asm("cvt.rn.f16x2.f32 %0, %1, %2;" : "=r"(w) : "f"(b), "f"(a));
    return w;
}
// swizzled byte offset inside a [row][64-word] tile: word ^= (row&7)<<2
__device__ __forceinline__ uint32_t swz(int r, uint32_t w) {
    return (uint32_t)r * 256u + ((w ^ (uint32_t)((r & 7) << 2)) << 2);
}
__device__ __forceinline__ void ldsm4(uint32_t addr, uint32_t* r) {
    asm volatile("ldmatrix.sync.aligned.m8n8.x4.shared.b16 {%0,%1,%2,%3}, [%4];"
                 : "=r"(r[0]), "=r"(r[1]), "=r"(r[2]), "=r"(r[3]) : "r"(addr));
}
__device__ __forceinline__ void mma_f16(float* d, const uint32_t* a, uint32_t b0, uint32_t b1) {
    asm volatile(
        "mma.sync.aligned.m16n8k16.row.col.f32.f16.f16.f32 "
        "{%0,%1,%2,%3},{%4,%5,%6,%7},{%8,%9},{%0,%1,%2,%3};"
        : "+f"(d[0]), "+f"(d[1]), "+f"(d[2]), "+f"(d[3])
        : "r"(a[0]), "r"(a[1]), "r"(a[2]), "r"(a[3]), "r"(b0), "r"(b1));
}
__device__ __forceinline__ void red4(float* p, float v0, float v1, float v2, float v3) {
    asm volatile("red.global.add.v4.f32 [%0], {%1,%2,%3,%4};"
                 :: "l"(p), "f"(v0), "f"(v1), "f"(v2), "f"(v3) : "memory");
}
__device__ __host__ __forceinline__ int perm_col(int n) {
    int p = n & 15;
    return (n & ~15) + ((p & 7) >> 1) * 4 + ((p >> 3) << 1) + (p & 1);
}

// ==================== prep ====================
__device__ __forceinline__ bool detect_is64(const long long* e64) {
    bool ok = true;
    #pragma unroll
    for (int i = 0; i < 8; i++)
        ok &= ((unsigned long long)e64[i] < (unsigned long long)NNODES);
    return ok;
}

__global__ void prep_kernel(const void* ei_raw, const void* batch_raw,
                            const float* __restrict__ W1, const float* __restrict__ W2,
                            const float* __restrict__ x, const float* __restrict__ u) {
    const bool is64 = detect_is64((const long long*)ei_raw);
    const long long* e64 = (const long long*)ei_raw;
    const int*       e32 = (const int*)ei_raw;
    const long long* b64 = (const long long*)batch_raw;
    const int*       b32 = (const int*)batch_raw;

    const int i0 = blockIdx.x * blockDim.x + threadIdx.x;
    const int stride = gridDim.x * blockDim.x;

    for (int e = i0; e < NEDGES; e += stride) {
        g_src[e] = is64 ? (int)e64[e]          : e32[e];
        g_dst[e] = is64 ? (int)e64[NEDGES + e] : e32[NEDGES + e];
    }
    for (int n = i0; n < NNODES; n += stride)
        g_batch[n] = is64 ? (int)b64[n] : b32[n];

    float4* p = (float4*)g_agg;
    const int nz = NNODES * OUTD / 4;
    float4 z = make_float4(0.f, 0.f, 0.f, 0.f);
    for (int i = i0; i < nz; i += stride) p[i] = z;

    // x -> fp16 (identical cvt.rn rounding as the old in-kernel conversion)
    {
        const float2* x2 = (const float2*)x;
        uint32_t* xo = (uint32_t*)g_x16;
        for (int i = i0; i < NNODES * 16; i += stride) {
            float2 v = x2[i];
            xo[i] = pack_f16(v.x, v.y);
        }
        const float2* u2 = (const float2*)u;
        uint32_t* uo = (uint32_t*)g_u16;
        for (int i = i0; i < 64 * 16; i += stride) {
            float2 v = u2[i];
            uo[i] = pack_f16(v.x, v.y);
        }
    }

    for (int q = i0; q < 4096; q += stride) {   // 64 n x 64 k-pairs
        int n = q >> 6, k = (q & 63) << 1;
        int l = perm_col(n);
        uint32_t off = swz(n, (uint32_t)(k >> 1));
        *(uint32_t*)(g_w1f16 + off) =
            pack_f16(W1[(size_t)k * OUTD + l], W1[(size_t)(k + 1) * OUTD + l]);
        *(uint32_t*)(g_w2f16 + off) =
            pack_f16(W2[(size_t)k * OUTD + l], W2[(size_t)(k + 1) * OUTD + l]);
    }
}

// ==================== shared pieces ====================
__device__ __forceinline__ void init_acc(const float* bias, int nh, int lane, float acc[4][4]) {
    #pragma unroll
    for (int jl = 0; jl < 4; jl++) {
        int np = nh * 2 + (jl >> 1);
        int c = np * 16 + (lane & 3) * 4 + (jl & 1) * 2;
        float b0 = bias[c], b1 = bias[c + 1];
        acc[jl][0] = b0; acc[jl][1] = b1; acc[jl][2] = b0; acc[jl][3] = b1;
    }
}

// half of the fp16 GEMM: ks in [ks0, ks0+4)
__device__ __forceinline__ void gemm_half(uint32_t sb, uint32_t aOff, uint32_t bOff,
                                          int mt, int nh, int lane,
                                          float acc[4][4], int ks0) {
    const int j  = lane >> 3;
    const int rr = lane & 7;
    const uint32_t xo = (uint32_t)(rr << 2);
    const int rowA = mt * 16 + ((j & 1) << 3) + rr;
    const int rowB = ((j & 1) << 3) + rr;
    const uint32_t ksg = (uint32_t)((j >> 1) << 2);

    #pragma unroll
    for (int kk = 0; kk < 4; kk++) {
        const int ks = ks0 + kk;
        const uint32_t byte = (((uint32_t)(ks * 8) + ksg) ^ xo) << 2;
        uint32_t a[4];
        ldsm4(sb + aOff + (uint32_t)rowA * 256 + byte, a);
        #pragma unroll
        for (int p = 0; p < 2; p++) {
            const int np = nh * 2 + p;
            uint32_t b[4];
            ldsm4(sb + bOff + (uint32_t)(rowB + np * 16) * 256 + byte, b);
            mma_f16(acc[2*p],   a, b[0], b[2]);
            mma_f16(acc[2*p+1], a, b[1], b[3]);
        }
    }
}

// ==================== edge kernel gather ====================
// Thread owns (row r = tid&127, seg = tid>>7 in 0..3) and handles 5 chunks:
//   dest-x fp16 16B (words seg*4), src-x fp16 16B (16+seg*4),
//   ea fp32 float4 x2 (words 32+seg*2 and 40+seg*2), u fp16 16B (48+seg*4).
__device__ __forceinline__ void gather_h1(
    const uint4* x16, const float4* ea4,
    const int* sDst, const int* sSrc,
    long long eBase, int t, int r, int seg,
    uint4& gd, uint4& gs, float4& e0)
{
    int row = t * MTILE + r;
    gd = x16[(size_t)sDst[row] * 4 + seg];
    gs = x16[(size_t)sSrc[row] * 4 + seg];
    e0 = ea4[(size_t)(eBase + row) * 8 + seg];
}
__device__ __forceinline__ void gather_h2(
    const uint4* u16, const float4* ea4,
    const int* sBB, long long eBase, int t, int r, int seg,
    float4& e1, uint4& gu)
{
    int row = t * MTILE + r;
    e1 = ea4[(size_t)(eBase + row) * 8 + seg + 4];
    gu = u16[(size_t)sBB[row] * 4 + seg];
}
__device__ __forceinline__ void stash_h1(char* smem, uint32_t aOff, int r, int seg,
                                         const uint4& gd, const uint4& gs, const float4& e0)
{
    *(uint4*)(smem + aOff + swz(r, (uint32_t)(seg * 4)))      = gd;
    *(uint4*)(smem + aOff + swz(r, (uint32_t)(16 + seg * 4))) = gs;
    uint32_t w0 = pack_f16(e0.x, e0.y), w1 = pack_f16(e0.z, e0.w);
    unsigned long long dw = (unsigned long long)w0 | ((unsigned long long)w1 << 32);
    *(unsigned long long*)(smem + aOff + swz(r, (uint32_t)(32 + seg * 2))) = dw;
}
__device__ __forceinline__ void stash_h2(char* smem, uint32_t aOff, int r, int seg,
                                         const float4& e1, const uint4& gu)
{
    uint32_t w0 = pack_f16(e1.x, e1.y), w1 = pack_f16(e1.z, e1.w);
    unsigned long long dw = (unsigned long long)w0 | ((unsigned long long)w1 << 32);
    *(unsigned long long*)(smem + aOff + swz(r, (uint32_t)(40 + seg * 2))) = dw;
    *(uint4*)(smem + aOff + swz(r, (uint32_t)(48 + seg * 4))) = gu;
}

__global__ void __launch_bounds__(THREADS, 2) edge_kernel(
    const float* __restrict__ ea, const float* __restrict__ b1)
{
    extern __shared__ char smem[];
    const uint32_t sb = smem_u32(smem);
    const int tid = threadIdx.x;
    const int lane = tid & 31, warp = tid >> 5;
    const int mt = warp >> 1, nh = warp & 1;
    const int gr = tid & 127, gseg = tid >> 7;

    int* sDst = (int*)(smem + E_DST);
    int* sSrc = (int*)(smem + E_SRC);
    int* sBB  = (int*)(smem + E_BB);

    const long long eBase = (long long)blockIdx.x * (MTILE * TPB);
    const int nt = (blockIdx.x == EDGE_BLOCKS - 1)
                 ? (int)((NEDGES - eBase) / MTILE) : TPB;

    {   // this block's edge indices (up to 1024)
        int nedge = nt * MTILE;
        #pragma unroll
        for (int i = 0; i < 2; i++) {
            int o = tid + i * THREADS;
            if (o < nedge) {
                int e = (int)eBase + o;
                int s = g_src[e];
                sSrc[o] = s;
                sDst[o] = g_dst[e];
                sBB[o]  = g_batch[s];
            }
        }
    }
    if (tid < OUTD) ((float*)(smem + E_BIAS))[tid] = b1[tid];
    {   // W1 fp16 (16KB) once per block
        const float4* w4 = (const float4*)g_w1f16;
        float4* d4 = (float4*)(smem + E_B);
        #pragma unroll
        for (int i = 0; i < 1024 / THREADS; i++)
            d4[tid + i * THREADS] = w4[tid + i * THREADS];
    }
    __syncthreads();   // indices visible

    const uint4*  x16 = (const uint4*)g_x16;
    const uint4*  u16 = (const uint4*)g_u16;
    const float4* ea4 = (const float4*)ea;

    // prologue: fill A0 for tile 0
    {
        uint4 gd, gs, gu; float4 e0, e1;
        gather_h1(x16, ea4, sDst, sSrc, eBase, 0, gr, gseg, gd, gs, e0);
        stash_h1(smem, E_A0, gr, gseg, gd, gs, e0);
        gather_h2(u16, ea4, sBB, eBase, 0, gr, gseg, e1, gu);
        stash_h2(smem, E_A0, gr, gseg, e1, gu);
    }
    __syncthreads();

    const int ra = mt * 16 + (lane >> 2);
    const int rb = ra + 8;

    for (int t = 0; t < nt; t++) {
        const uint32_t aCur = (t & 1) ? E_A1 : E_A0;
        const uint32_t aNxt = (t & 1) ? E_A0 : E_A1;

        float acc[4][4];
        init_acc((const float*)(smem + E_BIAS), nh, lane, acc);

        uint4 gd, gs, gu; float4 e0, e1;
        if (t + 1 < nt)
            gather_h1(x16, ea4, sDst, sSrc, eBase, t + 1, gr, gseg, gd, gs, e0);

        gemm_half(sb, aCur, E_B, mt, nh, lane, acc, 0);   // hides LDG latency

        if (t + 1 < nt) {
            stash_h1(smem, aNxt, gr, gseg, gd, gs, e0);
            gather_h2(u16, ea4, sBB, eBase, t + 1, gr, gseg, e1, gu);
        }

        gemm_half(sb, aCur, E_B, mt, nh, lane, acc, 4);

        if (t + 1 < nt)
            stash_h2(smem, aNxt, gr, gseg, e1, gu);

        {   // relu + v4 scatter (bias already in acc)
            const int da = sDst[t * MTILE + ra];
            const int db = sDst[t * MTILE + rb];
            float* pa = g_agg + (size_t)da * OUTD + (lane & 3) * 4;
            float* pb = g_agg + (size_t)db * OUTD + (lane & 3) * 4;
            #pragma unroll
            for (int p = 0; p < 2; p++) {
                const int np = nh * 2 + p;
                red4(pa + np * 16,
                     fmaxf(acc[2*p][0], 0.f),   fmaxf(acc[2*p][1], 0.f),
                     fmaxf(acc[2*p+1][0], 0.f), fmaxf(acc[2*p+1][1], 0.f));
                red4(pb + np * 16,
                     fmaxf(acc[2*p][2], 0.f),   fmaxf(acc[2*p][3], 0.f),
                     fmaxf(acc[2*p+1][2], 0.f), fmaxf(acc[2*p+1][3], 0.f));
            }
        }
        __syncthreads();   // all reads of aCur done; next tile stash safe
    }
}

// ==================== node kernel (fp16 1-pass) ====================
__global__ void __launch_bounds__(THREADS, 2) node_kernel(
    const float* __restrict__ x, const float* __restrict__ u,
    const float* __restrict__ b2, float* __restrict__ out)
{
    extern __shared__ char smem[];
    const uint32_t sb = smem_u32(smem);
    const int tid = threadIdx.x;
    const long long n0 = (long long)blockIdx.x * MTILE;

    int* sBB = (int*)(smem + N_BB);
    if (tid < MTILE) {
        long long nn = n0 + tid;
        if (nn >= NNODES) nn = NNODES - 1;
        sBB[tid] = g_batch[nn];
    }
    if (tid < OUTD) ((float*)(smem + N_BIAS))[tid] = b2[tid];
    {   // copy W2 fp16
        const float4* w4 = (const float4*)g_w2f16;
        float4* d4 = (float4*)(smem + N_B);
        #pragma unroll
        for (int i = 0; i < 1024 / THREADS; i++)
            d4[tid + i * THREADS] = w4[tid + i * THREADS];
    }
    __syncthreads();

    {   // batched gather: full 128x32 float4 coverage = 8 iters/thread
        const float4* x4 = (const float4*)x;
        const float4* u4 = (const float4*)u;
        const float4* agg4 = (const float4*)g_agg;
        float4 gv[8];
        int grr[8], gsg[8];
        #pragma unroll
        for (int it = 0; it < 8; it++) {
            int idx = tid + it * THREADS;
            int r = idx >> 5, seg = idx & 31;
            grr[it] = r; gsg[it] = seg;
            long long nn = n0 + r;
            if (nn >= NNODES) nn = NNODES - 1;
            const float4* p;
            if (seg < 8)       p = x4   + (size_t)nn * 8 + seg;
            else if (seg < 24) p = agg4 + (size_t)nn * 16 + (seg - 8);
            else               p = u4   + (size_t)sBB[r] * 8 + (seg - 24);
            gv[it] = *p;
        }
        #pragma unroll
        for (int it = 0; it < 8; it++) {
            uint32_t w0 = (uint32_t)(gsg[it] * 2);
            *(uint32_t*)(smem + N_A + swz(grr[it], w0))     = pack_f16(gv[it].x, gv[it].y);
            *(uint32_t*)(smem + N_A + swz(grr[it], w0 + 1)) = pack_f16(gv[it].z, gv[it].w);
        }
    }
    __syncthreads();

    const int lane = tid & 31, warp = tid >> 5;
    const int mt = warp >> 1, nh = warp & 1;
    float acc[4][4];
    init_acc((const float*)(smem + N_BIAS), nh, lane, acc);

    gemm_half(sb, N_A, N_B, mt, nh, lane, acc, 0);
    gemm_half(sb, N_A, N_B, mt, nh, lane, acc, 4);

    {   // relu + float4 store
        long long ra = n0 + mt * 16 + (lane >> 2);
        long long rb = ra + 8;
        #pragma unroll
        for (int p = 0; p < 2; p++) {
            const int np = nh * 2 + p;
            int c = np * 16 + (lane & 3) * 4;
            if (ra < NNODES)
                *(float4*)(out + (size_t)ra * OUTD + c) = make_float4(
                    fmaxf(acc[2*p][0], 0.f),   fmaxf(acc[2*p][1], 0.f),
                    fmaxf(acc[2*p+1][0], 0.f), fmaxf(acc[2*p+1][1], 0.f));
            if (rb < NNODES)
                *(float4*)(out + (size_t)rb * OUTD + c) = make_float4(
                    fmaxf(acc[2*p][2], 0.f),   fmaxf(acc[2*p][3], 0.f),
                    fmaxf(acc[2*p+1][2], 0.f), fmaxf(acc[2*p+1][3], 0.f));
        }
    }
}

// ==================== launcher ====================
extern "C" void kernel_launch(void* const* d_in, const int* in_sizes, int n_in,
                              void* d_out, int out_size) {
    const float* x     = (const float*)d_in[0];
    const void*  ei    = d_in[1];
    const float* ea    = (const float*)d_in[2];
    const float* u     = (const float*)d_in[3];
    const void*  batch = d_in[4];
    const float* W1    = (const float*)d_in[5];
    const float* b1    = (const float*)d_in[6];
    const float* W2    = (const float*)d_in[7];
    const float* b2    = (const float*)d_in[8];
    float* out = (float*)d_out;

    cudaFuncSetAttribute(edge_kernel, cudaFuncAttributeMaxDynamicSharedMemorySize, E_SZ);
    cudaFuncSetAttribute(node_kernel, cudaFuncAttributeMaxDynamicSharedMemorySize, N_SZ);

    prep_kernel<<<1480, 256>>>(ei, batch, W1, W2, x, u);
    edge_kernel<<<EDGE_BLOCKS, THREADS, E_SZ>>>(ea, b1);
    node_kernel<<<NODE_BLOCKS, THREADS, N_SZ>>>(x, u, b2, out);
}

// round 15
// speedup vs baseline: 1.1791x; 1.1791x over previous
#include <cuda_runtime.h>
#include <cuda_bf16.h>
#include <cstdint>
#include <cstddef>

#define NEDGES  1600000
#define NNODES  100000
#define OUTD    64
#define MTILE   128
#define THREADS 512
#define TPB     4
#define EDGE_BLOCKS (NEDGES / (MTILE * TPB))          // 3125, no tail
#define NODE_BLOCKS ((NNODES + MTILE - 1) / MTILE)    // 782

// ---- edge kernel smem layout (fp16, double-buffered A) ----
#define E_BIAS 0         // 64 floats
#define E_DST  256       // 512 ints
#define E_SRC  2304
#define E_BB   4352
#define E_A0   7168      // 128x128 fp16 (32KB), swizzled 256B rows
#define E_A1   (E_A0 + 32768)
#define E_B    (E_A1 + 32768)   // 64x128 fp16 (16KB)
#define E_SZ   (E_B + 16384)    // 89088

// ---- node kernel smem layout (fp16 single buffer) ----
#define N_BIAS 0
#define N_BB   256       // 128 ints
#define N_A    2048      // 32KB
#define N_B    (N_A + 32768)
#define N_SZ   (N_B + 16384)    // 51200

// ---- device scratch ----
__device__ float g_agg[(size_t)NNODES * OUTD];
__device__ int   g_src[NEDGES];
__device__ int   g_dst[NEDGES];
__device__ int   g_batch[NNODES];
__device__ __align__(16) unsigned short g_x16[(size_t)NNODES * 32];  // x in fp16
__device__ __align__(16) unsigned short g_u16[64 * 32];              // u in fp16
__device__ __align__(16) unsigned char g_w1f16[16384];   // W1 fp16, B^T swizzled
__device__ __align__(16) unsigned char g_w2f16[16384];   // W2 fp16, B^T swizzled

// ================= helpers =================
__device__ __forceinline__ uint32_t smem_u32(const void* p) {
    uint32_t a;
    asm("{ .reg .u64 t; cvta.to.shared.u64 t, %1; cvt.u32.u64 %0, t; }" : "=r"(a) : "l"(p));
    return a;
}
__device__ __forceinline__ uint32_t pack_f16(float a, float b) {
    uint32_t w;
    asm("cvt.rn.f16x2.f32 %0, %1, %2;" : "=r"(w) : "f"(b), "f"(a));
    return w;
}
// swizzled byte offset inside a [row][64-word] tile: word ^= (row&7)<<2
__device__ __forceinline__ uint32_t swz(int r, uint32_t w) {
    return (uint32_t)r * 256u + ((w ^ (uint32_t)((r & 7) << 2)) << 2);
}
__device__ __forceinline__ void ldsm4(uint32_t addr, uint32_t* r) {
    asm volatile("ldmatrix.sync.aligned.m8n8.x4.shared.b16 {%0,%1,%2,%3}, [%4];"
                 : "=r"(r[0]), "=r"(r[1]), "=r"(r[2]), "=r"(r[3]) : "r"(addr));
}
__device__ __forceinline__ void mma_f16(float* d, const uint32_t* a, uint32_t b0, uint32_t b1) {
    asm volatile(
        "mma.sync.aligned.m16n8k16.row.col.f32.f16.f16.f32 "
        "{%0,%1,%2,%3},{%4,%5,%6,%7},{%8,%9},{%0,%1,%2,%3};"
        : "+f"(d[0]), "+f"(d[1]), "+f"(d[2]), "+f"(d[3])
        : "r"(a[0]), "r"(a[1]), "r"(a[2]), "r"(a[3]), "r"(b0), "r"(b1));
}
__device__ __forceinline__ void red4(float* p, float v0, float v1, float v2, float v3) {
    asm volatile("red.global.add.v4.f32 [%0], {%1,%2,%3,%4};"
                 :: "l"(p), "f"(v0), "f"(v1), "f"(v2), "f"(v3) : "memory");
}
__device__ __host__ __forceinline__ int perm_col(int n) {
    int p = n & 15;
    return (n & ~15) + ((p & 7) >> 1) * 4 + ((p >> 3) << 1) + (p & 1);
}

// ==================== prep ====================
__device__ __forceinline__ bool detect_is64(const long long* e64) {
    bool ok = true;
    #pragma unroll
    for (int i = 0; i < 8; i++)
        ok &= ((unsigned long long)e64[i] < (unsigned long long)NNODES);
    return ok;
}

__global__ void prep_kernel(const void* ei_raw, const void* batch_raw,
                            const float* __restrict__ W1, const float* __restrict__ W2,
                            const float* __restrict__ x, const float* __restrict__ u) {
    const bool is64 = detect_is64((const long long*)ei_raw);
    const long long* e64 = (const long long*)ei_raw;
    const int*       e32 = (const int*)ei_raw;
    const long long* b64 = (const long long*)batch_raw;
    const int*       b32 = (const int*)batch_raw;

    const int i0 = blockIdx.x * blockDim.x + threadIdx.x;
    const int stride = gridDim.x * blockDim.x;

    for (int e = i0; e < NEDGES; e += stride) {
        g_src[e] = is64 ? (int)e64[e]          : e32[e];
        g_dst[e] = is64 ? (int)e64[NEDGES + e] : e32[NEDGES + e];
    }
    for (int n = i0; n < NNODES; n += stride)
        g_batch[n] = is64 ? (int)b64[n] : b32[n];

    float4* p = (float4*)g_agg;
    const int nz = NNODES * OUTD / 4;
    float4 z = make_float4(0.f, 0.f, 0.f, 0.f);
    for (int i = i0; i < nz; i += stride) p[i] = z;

    // x, u -> fp16 (identical cvt.rn rounding as in-kernel conversion)
    {
        const float2* x2 = (const float2*)x;
        uint32_t* xo = (uint32_t*)g_x16;
        for (int i = i0; i < NNODES * 16; i += stride) {
            float2 v = x2[i];
            xo[i] = pack_f16(v.x, v.y);
        }
        const float2* u2 = (const float2*)u;
        uint32_t* uo = (uint32_t*)g_u16;
        for (int i = i0; i < 64 * 16; i += stride) {
            float2 v = u2[i];
            uo[i] = pack_f16(v.x, v.y);
        }
    }

    for (int q = i0; q < 4096; q += stride) {   // 64 n x 64 k-pairs
        int n = q >> 6, k = (q & 63) << 1;
        int l = perm_col(n);
        uint32_t off = swz(n, (uint32_t)(k >> 1));
        *(uint32_t*)(g_w1f16 + off) =
            pack_f16(W1[(size_t)k * OUTD + l], W1[(size_t)(k + 1) * OUTD + l]);
        *(uint32_t*)(g_w2f16 + off) =
            pack_f16(W2[(size_t)k * OUTD + l], W2[(size_t)(k + 1) * OUTD + l]);
    }
}

// ==================== shared pieces ====================
__device__ __forceinline__ void init_acc(const float* bias, int nh, int lane, float acc[4][4]) {
    #pragma unroll
    for (int jl = 0; jl < 4; jl++) {
        int np = nh * 2 + (jl >> 1);
        int c = np * 16 + (lane & 3) * 4 + (jl & 1) * 2;
        float b0 = bias[c], b1 = bias[c + 1];
        acc[jl][0] = b0; acc[jl][1] = b1; acc[jl][2] = b0; acc[jl][3] = b1;
    }
}

// half of the fp16 GEMM: ks in [ks0, ks0+4)
__device__ __forceinline__ void gemm_half(uint32_t sb, uint32_t aOff, uint32_t bOff,
                                          int mt, int nh, int lane,
                                          float acc[4][4], int ks0) {
    const int j  = lane >> 3;
    const int rr = lane & 7;
    const uint32_t xo = (uint32_t)(rr << 2);
    const int rowA = mt * 16 + ((j & 1) << 3) + rr;
    const int rowB = ((j & 1) << 3) + rr;
    const uint32_t ksg = (uint32_t)((j >> 1) << 2);

    #pragma unroll
    for (int kk = 0; kk < 4; kk++) {
        const int ks = ks0 + kk;
        const uint32_t byte = (((uint32_t)(ks * 8) + ksg) ^ xo) << 2;
        uint32_t a[4];
        ldsm4(sb + aOff + (uint32_t)rowA * 256 + byte, a);
        #pragma unroll
        for (int p = 0; p < 2; p++) {
            const int np = nh * 2 + p;
            uint32_t b[4];
            ldsm4(sb + bOff + (uint32_t)(rowB + np * 16) * 256 + byte, b);
            mma_f16(acc[2*p],   a, b[0], b[2]);
            mma_f16(acc[2*p+1], a, b[1], b[3]);
        }
    }
}

// ==================== edge gather: 20 chunks per row, 5 iters/thread ====================
// seg 0-3: dest-x uint4 -> words seg*4      | seg 4-7: src-x uint4 -> words seg*4
// seg 8-15: ea float4 (cvt) -> words 32+(seg-8)*2 | seg 16-19: u uint4 -> words 48+(seg-16)*4
__device__ __forceinline__ uint4 gather_one(
    const uint4* x16, const uint4* u16, const float4* ea4,
    const int* sDst, const int* sSrc, const int* sBB,
    long long eBase, int t, int r, int seg)
{
    int row = t * MTILE + r;
    if (seg < 4)       return x16[(size_t)sDst[row] * 4 + seg];
    else if (seg < 8)  return x16[(size_t)sSrc[row] * 4 + (seg - 4)];
    else if (seg < 16) {
        float4 v = ea4[(size_t)(eBase + row) * 8 + (seg - 8)];
        return *(uint4*)&v;
    }
    else               return u16[(size_t)sBB[row] * 4 + (seg - 16)];
}
__device__ __forceinline__ void stash_one(char* smem, uint32_t aOff, int r, int seg, uint4 v)
{
    if (seg < 8) {
        *(uint4*)(smem + aOff + swz(r, (uint32_t)(seg * 4))) = v;
    } else if (seg < 16) {
        float4 f = *(float4*)&v;
        uint32_t w0 = pack_f16(f.x, f.y), w1 = pack_f16(f.z, f.w);
        unsigned long long dw = (unsigned long long)w0 | ((unsigned long long)w1 << 32);
        *(unsigned long long*)(smem + aOff + swz(r, (uint32_t)(32 + (seg - 8) * 2))) = dw;
    } else {
        *(uint4*)(smem + aOff + swz(r, (uint32_t)(48 + (seg - 16) * 4))) = v;
    }
}

__global__ void __launch_bounds__(THREADS, 2) edge_kernel(
    const float* __restrict__ ea, const float* __restrict__ b1)
{
    extern __shared__ char smem[];
    const uint32_t sb = smem_u32(smem);
    const int tid = threadIdx.x;
    const int lane = tid & 31, warp = tid >> 5;
    const int mt = warp >> 1, nh = warp & 1;

    int* sDst = (int*)(smem + E_DST);
    int* sSrc = (int*)(smem + E_SRC);
    int* sBB  = (int*)(smem + E_BB);

    const long long eBase = (long long)blockIdx.x * (MTILE * TPB);
    {   // this block's 512 edge indices, one per thread
        int e = (int)eBase + tid;
        int s = g_src[e];
        sSrc[tid] = s;
        sDst[tid] = g_dst[e];
        sBB[tid]  = g_batch[s];
    }
    if (tid < OUTD) ((float*)(smem + E_BIAS))[tid] = b1[tid];
    {   // W1 fp16 (16KB) once per block
        const float4* w4 = (const float4*)g_w1f16;
        float4* d4 = (float4*)(smem + E_B);
        #pragma unroll
        for (int i = 0; i < 1024 / THREADS; i++)
            d4[tid + i * THREADS] = w4[tid + i * THREADS];
    }
    __syncthreads();   // indices visible

    const uint4*  x16 = (const uint4*)g_x16;
    const uint4*  u16 = (const uint4*)g_u16;
    const float4* ea4 = (const float4*)ea;

    // loop-invariant (row, seg) decomposition: 2560 chunks = 5 x 512
    int r5[5], s5[5];
    #pragma unroll
    for (int it = 0; it < 5; it++) {
        int idx = tid + it * THREADS;
        r5[it] = idx / 20;
        s5[it] = idx % 20;
    }

    // prologue: fill A0 for tile 0
    {
        uint4 gv[5];
        #pragma unroll
        for (int it = 0; it < 5; it++)
            gv[it] = gather_one(x16, u16, ea4, sDst, sSrc, sBB, eBase, 0, r5[it], s5[it]);
        #pragma unroll
        for (int it = 0; it < 5; it++)
            stash_one(smem, E_A0, r5[it], s5[it], gv[it]);
    }
    __syncthreads();

    const int ra = mt * 16 + (lane >> 2);
    const int rb = ra + 8;

    for (int t = 0; t < TPB; t++) {
        const uint32_t aCur = (t & 1) ? E_A1 : E_A0;
        const uint32_t aNxt = (t & 1) ? E_A0 : E_A1;

        float acc[4][4];
        init_acc((const float*)(smem + E_BIAS), nh, lane, acc);

        uint4 gv[3];
        if (t + 1 < TPB) {   // first 3 chunks of next tile's gather
            #pragma unroll
            for (int it = 0; it < 3; it++)
                gv[it] = gather_one(x16, u16, ea4, sDst, sSrc, sBB, eBase, t + 1, r5[it], s5[it]);
        }

        gemm_half(sb, aCur, E_B, mt, nh, lane, acc, 0);   // hides LDG latency

        if (t + 1 < TPB) {
            #pragma unroll
            for (int it = 0; it < 3; it++)
                stash_one(smem, aNxt, r5[it], s5[it], gv[it]);
            #pragma unroll
            for (int it = 0; it < 2; it++)
                gv[it] = gather_one(x16, u16, ea4, sDst, sSrc, sBB, eBase, t + 1, r5[3 + it], s5[3 + it]);
        }

        gemm_half(sb, aCur, E_B, mt, nh, lane, acc, 4);

        if (t + 1 < TPB) {
            #pragma unroll
            for (int it = 0; it < 2; it++)
                stash_one(smem, aNxt, r5[3 + it], s5[3 + it], gv[it]);
        }

        {   // relu + v4 scatter (bias already in acc)
            const int da = sDst[t * MTILE + ra];
            const int db = sDst[t * MTILE + rb];
            float* pa = g_agg + (size_t)da * OUTD + (lane & 3) * 4;
            float* pb = g_agg + (size_t)db * OUTD + (lane & 3) * 4;
            #pragma unroll
            for (int p = 0; p < 2; p++) {
                const int np = nh * 2 + p;
                red4(pa + np * 16,
                     fmaxf(acc[2*p][0], 0.f),   fmaxf(acc[2*p][1], 0.f),
                     fmaxf(acc[2*p+1][0], 0.f), fmaxf(acc[2*p+1][1], 0.f));
                red4(pb + np * 16,
                     fmaxf(acc[2*p][2], 0.f),   fmaxf(acc[2*p][3], 0.f),
                     fmaxf(acc[2*p+1][2], 0.f), fmaxf(acc[2*p+1][3], 0.f));
            }
        }
        __syncthreads();   // all reads of aCur done; next tile stash safe
    }
}

// ==================== node kernel (fp16 1-pass, R11 verbatim) ====================
__global__ void __launch_bounds__(THREADS, 2) node_kernel(
    const float* __restrict__ x, const float* __restrict__ u,
    const float* __restrict__ b2, float* __restrict__ out)
{
    extern __shared__ char smem[];
    const uint32_t sb = smem_u32(smem);
    const int tid = threadIdx.x;
    const long long n0 = (long long)blockIdx.x * MTILE;

    int* sBB = (int*)(smem + N_BB);
    if (tid < MTILE) {
        long long nn = n0 + tid;
        if (nn >= NNODES) nn = NNODES - 1;
        sBB[tid] = g_batch[nn];
    }
    if (tid < OUTD) ((float*)(smem + N_BIAS))[tid] = b2[tid];
    {   // copy W2 fp16
        const float4* w4 = (const float4*)g_w2f16;
        float4* d4 = (float4*)(smem + N_B);
        #pragma unroll
        for (int i = 0; i < 1024 / THREADS; i++)
            d4[tid + i * THREADS] = w4[tid + i * THREADS];
    }
    __syncthreads();

    {   // batched gather: full 128x32 float4 coverage = 8 iters/thread
        const float4* x4 = (const float4*)x;
        const float4* u4 = (const float4*)u;
        const float4* agg4 = (const float4*)g_agg;
        float4 gv[8];
        int grr[8], gsg[8];
        #pragma unroll
        for (int it = 0; it < 8; it++) {
            int idx = tid + it * THREADS;
            int r = idx >> 5, seg = idx & 31;
            grr[it] = r; gsg[it] = seg;
            long long nn = n0 + r;
            if (nn >= NNODES) nn = NNODES - 1;
            const float4* p;
            if (seg < 8)       p = x4   + (size_t)nn * 8 + seg;
            else if (seg < 24) p = agg4 + (size_t)nn * 16 + (seg - 8);
            else               p = u4   + (size_t)sBB[r] * 8 + (seg - 24);
            gv[it] = *p;
        }
        #pragma unroll
        for (int it = 0; it < 8; it++) {
            uint32_t w0 = (uint32_t)(gsg[it] * 2);
            *(uint32_t*)(smem + N_A + swz(grr[it], w0))     = pack_f16(gv[it].x, gv[it].y);
            *(uint32_t*)(smem + N_A + swz(grr[it], w0 + 1)) = pack_f16(gv[it].z, gv[it].w);
        }
    }
    __syncthreads();

    const int lane = tid & 31, warp = tid >> 5;
    const int mt = warp >> 1, nh = warp & 1;
    float acc[4][4];
    init_acc((const float*)(smem + N_BIAS), nh, lane, acc);

    gemm_half(sb, N_A, N_B, mt, nh, lane, acc, 0);
    gemm_half(sb, N_A, N_B, mt, nh, lane, acc, 4);

    {   // relu + float4 store
        long long ra = n0 + mt * 16 + (lane >> 2);
        long long rb = ra + 8;
        #pragma unroll
        for (int p = 0; p < 2; p++) {
            const int np = nh * 2 + p;
            int c = np * 16 + (lane & 3) * 4;
            if (ra < NNODES)
                *(float4*)(out + (size_t)ra * OUTD + c) = make_float4(
                    fmaxf(acc[2*p][0], 0.f),   fmaxf(acc[2*p][1], 0.f),
                    fmaxf(acc[2*p+1][0], 0.f), fmaxf(acc[2*p+1][1], 0.f));
            if (rb < NNODES)
                *(float4*)(out + (size_t)rb * OUTD + c) = make_float4(
                    fmaxf(acc[2*p][2], 0.f),   fmaxf(acc[2*p][3], 0.f),
                    fmaxf(acc[2*p+1][2], 0.f), fmaxf(acc[2*p+1][3], 0.f));
        }
    }
}

// ==================== launcher ====================
extern "C" void kernel_launch(void* const* d_in, const int* in_sizes, int n_in,
                              void* d_out, int out_size) {
    const float* x     = (const float*)d_in[0];
    const void*  ei    = d_in[1];
    const float* ea    = (const float*)d_in[2];
    const float* u     = (const float*)d_in[3];
    const void*  batch = d_in[4];
    const float* W1    = (const float*)d_in[5];
    const float* b1    = (const float*)d_in[6];
    const float* W2    = (const float*)d_in[7];
    const float* b2    = (const float*)d_in[8];
    float* out = (float*)d_out;

    cudaFuncSetAttribute(edge_kernel, cudaFuncAttributeMaxDynamicSharedMemorySize, E_SZ);
    cudaFuncSetAttribute(node_kernel, cudaFuncAttributeMaxDynamicSharedMemorySize, N_SZ);

    prep_kernel<<<1480, 256>>>(ei, batch, W1, W2, x, u);
    edge_kernel<<<EDGE_BLOCKS, THREADS, E_SZ>>>(ea, b1);
    node_kernel<<<NODE_BLOCKS, THREADS, N_SZ>>>(x, u, b2, out);
}